// round 17
// baseline (speedup 1.0000x reference)
#include <cuda_runtime.h>
#include <math.h>

#define Bn 2
#define CIN 64
#define CI 16
#define Hn 96
#define Wn 96
#define HWn 9216
#define PSn 7
#define Kn 100
#define WSn 21
#define NCn 441
#define NHn 24
#define NWn 24
#define Qn 576
#define S0n 4
#define SCALEF 10.0f
#define TH 27
#define TW 31
#define TCH (TH * TW)          // 837 words per channel
#define TILE_WORDS (CI * TCH)  // 13392

// ------------------------- device scratch (no allocs allowed) ----------------
__device__ float g_theta[Bn * CI * HWn];
__device__ float g_phi[Bn * CI * HWn];
__device__ float g_g[Bn * CI * HWn];
__device__ float g_zimg[Bn * CI * HWn];
__device__ float g_cnt[HWn];
__device__ float g_A[CIN * CI];
__device__ float g_b2[CIN];

__device__ __forceinline__ int clampi(int v, int hi) { return min(max(v, 0), hi); }

// ------------------------- zero scratch --------------------------------------
__global__ void zero_kernel() {
    int i = blockIdx.x * blockDim.x + threadIdx.x;
    if (i < Bn * CI * HWn) g_zimg[i] = 0.0f;
    if (i < HWn) g_cnt[i] = 0.0f;
}

// ------------------------- 1x1 projections theta/phi/g -----------------------
__global__ void proj_kernel(const float* __restrict__ vid,
                            const float* __restrict__ wt, const float* __restrict__ bt,
                            const float* __restrict__ wp, const float* __restrict__ bp,
                            const float* __restrict__ wg, const float* __restrict__ bg) {
    __shared__ float sw[3 * CI * CIN];
    __shared__ float sb[3 * CI];
    int tid = threadIdx.x;
    for (int i = tid; i < CI * CIN; i += blockDim.x) {
        sw[i] = wt[i];
        sw[CI * CIN + i] = wp[i];
        sw[2 * CI * CIN + i] = wg[i];
    }
    if (tid < CI) { sb[tid] = bt[tid]; sb[CI + tid] = bp[tid]; sb[2 * CI + tid] = bg[tid]; }
    __syncthreads();

    int idx = blockIdx.x * blockDim.x + tid;
    if (idx >= Bn * HWn * 3) return;
    int grp = idx / (Bn * HWn);       // 0=theta 1=phi 2=g
    int pix = idx % (Bn * HWn);
    int b = pix / HWn, hw = pix % HWn;

    float x[CIN];
#pragma unroll
    for (int c = 0; c < CIN; c++) x[c] = vid[(b * CIN + c) * HWn + hw];

    const float* w = sw + grp * CI * CIN;
    float* dst = (grp == 0 ? g_theta : (grp == 1 ? g_phi : g_g)) + b * CI * HWn + hw;
#pragma unroll 4
    for (int o = 0; o < CI; o++) {
        float a = sb[grp * CI + o];
#pragma unroll
        for (int c = 0; c < CIN; c++) a = fmaf(w[o * CIN + c], x[c], a);
        dst[o * HWn] = a;
    }
}

// ------------------------- precompute fused epilogue weights -----------------
__global__ void precomp_kernel(const float* __restrict__ w_w, const float* __restrict__ b_w,
                               const float* __restrict__ w_c33, const float* __restrict__ b_c33) {
    int e = blockIdx.x * blockDim.x + threadIdx.x;
    if (e < CIN * CI) {
        int o = e / CI, ci = e % CI;
        float a = 0.0f;
        for (int c = 0; c < CIN; c++) a = fmaf(w_c33[o * (2 * CIN) + c], w_w[c * CI + ci], a);
        g_A[e] = a;
    }
    if (e < CIN) {
        float a = b_c33[e];
        for (int c = 0; c < CIN; c++) a = fmaf(w_c33[e * (2 * CIN) + c], b_w[c], a);
        g_b2[e] = a;
    }
}

// ------------------------- fused attention kernel ----------------------------
// One block per (batch, query PAIR): queries (qi,qj0) and (qi,qj0+4) share a
// 27x31 tile. Phases: stage phi -> scores(x2) -> topk(x2) -> restage g into the
// SAME tile -> weighted sum + scatter.
//
// smem layout (float words):
//   [0,13392)       tile (phi, then g)
//   [13392,13592)   sel_i  [2][100]        (persists across restage)
//   [13592,13792)   sel_w  [2][100]        (persists)
//   phase A (scores/topk):
//     [13792,15360) sTheta [2][784]
//     [15360,16242) scores [2][441]
//     [16242,17124) ukeys  [2][441]
//     [17124,17380) hist   [256]
//   phase B (z) overlay:
//     [13792,15192) sel_r27 [2][100][7]
//     [15192,16592) sel_c   [2][100][7]
#define SMEM_WORDS 17380

__global__ void __launch_bounds__(256, 3) attn_kernel() {
    extern __shared__ float sm[];
    float* sTile = sm;
    int* sel_i = (int*)(sm + 13392);
    float* sel_w = sm + 13592;
    float* sTheta = sm + 13792;
    float* scores = sm + 15360;
    unsigned* ukeys = (unsigned*)(sm + 16242);
    unsigned* hist = (unsigned*)(sm + 17124);
    int* sel_r27 = (int*)(sm + 13792);
    int* sel_c = (int*)(sm + 15192);

    __shared__ int s_bucket, s_above, s_eqc, s_nsel;
    __shared__ float s_sum[2], s_m, s_wmax[8];
    __shared__ unsigned s_scan[8];

    int tid = threadIdx.x;
    int blk = blockIdx.x;
    int b = blk / (Qn / 2);
    int pq = blk % (Qn / 2);
    int qi = (pq / (NWn / 2)) * S0n;
    int qj0 = (pq % (NWn / 2)) * 8;          // query A col; query B = qj0+4

    int row0 = min(max(qi - 13, 0), Hn - TH);
    int col0A = min(max(qj0 - 13, 0), Hn - TH);
    int u0 = min(col0A, Wn - TW);            // tile col origin, width 31

    // ---- stage phi tile + theta patches ----
    const float* phiB = g_phi + b * CI * HWn;
    for (int t = tid; t < TILE_WORDS; t += 256) {
        int c = t / TCH;
        int rem = t % TCH;
        int rr = rem / TW, cc = rem % TW;
        sTile[t] = phiB[c * HWn + (row0 + rr) * Wn + (u0 + cc)];
    }
    const float* thB = g_theta + b * CI * HWn;
    for (int t = tid; t < 2 * CI * 49; t += 256) {
        int q = t / 784;
        int rem = t % 784;
        int c = rem / 49, pi = (rem % 49) / 7, pj = rem % 7;
        int qj = qj0 + 4 * q;
        sTheta[t] = thB[c * HWn + clampi(qi + pi - 3, Hn - 1) * Wn + clampi(qj + pj - 3, Wn - 1)];
    }
    for (int i = tid; i < 2 * NCn; i += 256) scores[i] = 0.0f;
    if (b == 0 && tid < 98) {
        int q = tid / 49, pp = tid % 49;
        int pi = pp / 7, pj = pp % 7;
        int qj = qj0 + 4 * q;
        atomicAdd(&g_cnt[clampi(qi + pi - 3, Hn - 1) * Wn + clampi(qj + pj - 3, Wn - 1)], 1.0f);
    }
    __syncthreads();

    // ---- score phase: thread = (q, 8-ch group, di, 7-dj group) ----
    if (tid < 252) {
        int q = tid / 126;
        int rem = tid % 126;
        int cg = rem / 63;
        int rem2 = rem % 63;
        int di_idx = rem2 / 3;
        int g = rem2 % 3;
        int dj0 = g * 7 - 10;
        int cbase = cg * 8;
        int qj = qj0 + 4 * q;

        int ci = clampi(qi + di_idx - 10, Hn - 1);
        int rb[7];
#pragma unroll
        for (int p = 0; p < 7; p++) rb[p] = (clampi(ci + p - 3, Hn - 1) - row0) * TW;

        float acc[7];
#pragma unroll
        for (int t = 0; t < 7; t++) acc[t] = 0.0f;

        int base = qj + dj0;
        bool fast = (base >= 3) && (base <= 86);

        if (fast) {
            int colLo = base - 3 - u0;   // 13-wide window within tile
#pragma unroll 1
            for (int c = 0; c < 8; c++) {
                const float* thc = sTheta + q * 784 + (cbase + c) * 49;
                const float* phc = sTile + (cbase + c) * TCH + colLo;
#pragma unroll
                for (int pi = 0; pi < 7; pi++) {
                    const float* th = thc + pi * 7;
                    const float* ph = phc + rb[pi];
                    float thv[7];
#pragma unroll
                    for (int pj = 0; pj < 7; pj++) thv[pj] = th[pj];
                    float wv[13];
#pragma unroll
                    for (int x = 0; x < 13; x++) wv[x] = ph[x];
#pragma unroll
                    for (int t = 0; t < 7; t++)
#pragma unroll
                        for (int pj = 0; pj < 7; pj++)
                            acc[t] = fmaf(thv[pj], wv[t + pj], acc[t]);
                }
            }
        } else {
            // exact double-clamp fallback (border columns only)
#pragma unroll 1
            for (int t = 0; t < 7; t++) {
                int cj = clampi(qj + dj0 + t, Wn - 1);
                int cb[7];
#pragma unroll
                for (int p = 0; p < 7; p++) cb[p] = clampi(cj + p - 3, Wn - 1) - u0;
                float a = 0.0f;
#pragma unroll 1
                for (int c = 0; c < 8; c++) {
                    const float* th = sTheta + q * 784 + (cbase + c) * 49;
                    const float* ph = sTile + (cbase + c) * TCH;
#pragma unroll
                    for (int pi = 0; pi < 7; pi++) {
                        const float* pr = ph + rb[pi];
#pragma unroll
                        for (int pj = 0; pj < 7; pj++)
                            a = fmaf(th[pi * 7 + pj], pr[cb[pj]], a);
                    }
                }
                acc[t] = a;
            }
        }

#pragma unroll
        for (int t = 0; t < 7; t++)
            atomicAdd(&scores[q * NCn + di_idx * 21 + g * 7 + t], acc[t]);
    }
    __syncthreads();

    // ---- monotone keys (both queries) ----
    for (int i = tid; i < 2 * NCn; i += 256) {
        unsigned u = __float_as_uint(scores[i]);
        ukeys[i] = (u & 0x80000000u) ? ~u : (u | 0x80000000u);
    }
    __syncthreads();

    // ---- per-query: max, radix select, selection ----
    for (int q = 0; q < 2; q++) {
        float* scq = scores + q * NCn;
        unsigned* ukq = ukeys + q * NCn;

        // block max
        float lm = -3.4e38f;
        for (int i = tid; i < NCn; i += 256) lm = fmaxf(lm, scq[i]);
#pragma unroll
        for (int o = 16; o > 0; o >>= 1) lm = fmaxf(lm, __shfl_xor_sync(0xffffffffu, lm, o));
        if ((tid & 31) == 0) s_wmax[tid >> 5] = lm;
        __syncthreads();
        if (tid == 0) {
            float mm = s_wmax[0];
#pragma unroll
            for (int j = 1; j < 8; j++) mm = fmaxf(mm, s_wmax[j]);
            s_m = mm;
            s_eqc = 0;
            s_nsel = 0;
            s_sum[q] = 0.0f;
        }

        // exact 100th-largest via 4-pass radix select
        unsigned prefix = 0;
        int remaining = Kn;
        for (int shift = 24; shift >= 0; shift -= 8) {
            hist[tid] = 0u;
            __syncthreads();
            unsigned hm = (shift == 24) ? 0u : (0xFFFFFFFFu << (shift + 8));
            for (int i = tid; i < NCn; i += 256) {
                unsigned k = ukq[i];
                if ((k & hm) == prefix) atomicAdd(&hist[(k >> shift) & 255u], 1u);
            }
            __syncthreads();
            {
                unsigned v = hist[255 - tid];
                unsigned inc = v;
#pragma unroll
                for (int o = 1; o < 32; o <<= 1) {
                    unsigned n = __shfl_up_sync(0xffffffffu, inc, o);
                    if ((tid & 31) >= o) inc += n;
                }
                if ((tid & 31) == 31) s_scan[tid >> 5] = inc;
                __syncthreads();
                if (tid < 8) {
                    unsigned x = s_scan[tid];
#pragma unroll
                    for (int o = 1; o < 8; o <<= 1) {
                        unsigned n = __shfl_up_sync(0xffu, x, o);
                        if (tid >= o) x += n;
                    }
                    s_scan[tid] = x;
                }
                __syncthreads();
                unsigned offs = (tid >= 32) ? s_scan[(tid >> 5) - 1] : 0u;
                unsigned incl = inc + offs;
                unsigned excl = incl - v;
                if (excl < (unsigned)remaining && incl >= (unsigned)remaining) {
                    s_bucket = 255 - tid;
                    s_above = (int)excl;
                }
            }
            __syncthreads();
            prefix |= ((unsigned)s_bucket) << shift;
            remaining -= s_above;
            __syncthreads();
        }
        unsigned pivot = prefix;
        int needEq = remaining;
        float m = s_m;

        // select top-100: stash index + unnormalized weight
        for (int i = tid; i < NCn; i += 256) {
            unsigned k = ukq[i];
            bool take = false;
            if (k > pivot) take = true;
            else if (k == pivot) { if (atomicAdd(&s_eqc, 1) < needEq) take = true; }
            if (take) {
                int slot = atomicAdd(&s_nsel, 1);
                if (slot < Kn) {
                    float e = __expf(SCALEF * (scq[i] - m));
                    sel_i[q * Kn + slot] = i;
                    sel_w[q * Kn + slot] = e;
                    atomicAdd(&s_sum[q], e);
                }
            }
        }
        __syncthreads();
    }

    // ---- restage tile with g; build patch offsets in overlay ----
    const float* gB = g_g + b * CI * HWn;
    for (int t = tid; t < TILE_WORDS; t += 256) {
        int c = t / TCH;
        int rem = t % TCH;
        int rr = rem / TW, cc = rem % TW;
        sTile[t] = gB[c * HWn + (row0 + rr) * Wn + (u0 + cc)];
    }
    if (tid < 2 * Kn) {
        int q = tid / Kn, k = tid % Kn;
        int i = sel_i[q * Kn + k];
        int qj = qj0 + 4 * q;
        int di = i / WSn - 10, dj = i % WSn - 10;
        int ci = clampi(qi + di, Hn - 1), cj = clampi(qj + dj, Wn - 1);
#pragma unroll
        for (int p = 0; p < 7; p++) {
            sel_r27[(q * Kn + k) * 7 + p] = (clampi(ci + p - 3, Hn - 1) - row0) * TW;
            sel_c[(q * Kn + k) * 7 + p] = clampi(cj + p - 3, Wn - 1) - u0;
        }
    }
    __syncthreads();

    // ---- weighted patch sum: thread = (q, c, pi); 7 pj accumulators ----
    if (tid < 224) {
        int q = tid / 112;
        int ci_ = tid % 112;
        int c = ci_ / 7, pi = ci_ % 7;
        int qj = qj0 + 4 * q;
        float invs = 1.0f / s_sum[q];
        const float* gcBase = sTile + c * TCH;
        const float* swq = sel_w + q * Kn;
        const int* srq = sel_r27 + q * Kn * 7;
        const int* scq = sel_c + q * Kn * 7;

        float a7[7];
#pragma unroll
        for (int pj = 0; pj < 7; pj++) a7[pj] = 0.0f;
#pragma unroll 2
        for (int k = 0; k < Kn; k++) {
            float w = swq[k];
            const float* gg = gcBase + srq[k * 7 + pi];
            const int* cc = scq + k * 7;
#pragma unroll
            for (int pj = 0; pj < 7; pj++)
                a7[pj] = fmaf(w, gg[cc[pj]], a7[pj]);
        }
        int prr = clampi(qi + pi - 3, Hn - 1);
        float* dst = &g_zimg[(b * CI + c) * HWn + prr * Wn];
#pragma unroll
        for (int pj = 0; pj < 7; pj++)
            atomicAdd(dst + clampi(qj + pj - 3, Wn - 1), a7[pj] * invs);
    }
}

// ------------------------- fused output: out = A*(zimg/cnt) + w_c33_r*vid + b2
__global__ void out_kernel(const float* __restrict__ vid,
                           const float* __restrict__ wc, float* __restrict__ out) {
    __shared__ float sA[CIN * CI], sW2[CIN * CIN], sB2[CIN];
    int tid = threadIdx.x;
    for (int i = tid; i < CIN * CI; i += 256) sA[i] = g_A[i];
    for (int i = tid; i < CIN * CIN; i += 256) {
        int o = i / CIN, c = i % CIN;
        sW2[i] = wc[o * (2 * CIN) + CIN + c];
    }
    if (tid < CIN) sB2[tid] = g_b2[tid];
    __syncthreads();

    int idx = blockIdx.x * 256 + tid;
    if (idx >= Bn * HWn * 4) return;
    int grp = idx / (Bn * HWn);
    int pix = idx % (Bn * HWn);
    int b = pix / HWn, hw = pix % HWn;

    float invc = 1.0f / fmaxf(g_cnt[hw], 1.0f);
    float zv[CI];
#pragma unroll
    for (int ci = 0; ci < CI; ci++) zv[ci] = g_zimg[(b * CI + ci) * HWn + hw] * invc;
    float x[CIN];
#pragma unroll
    for (int c = 0; c < CIN; c++) x[c] = vid[(b * CIN + c) * HWn + hw];

    int o0 = grp * 16;
#pragma unroll 4
    for (int oo = 0; oo < 16; oo++) {
        int o = o0 + oo;
        float a = sB2[o];
#pragma unroll
        for (int ci = 0; ci < CI; ci++) a = fmaf(sA[o * CI + ci], zv[ci], a);
#pragma unroll
        for (int c = 0; c < CIN; c++) a = fmaf(sW2[o * CIN + c], x[c], a);
        out[(b * CIN + o) * HWn + hw] = a;
    }
}

// ------------------------- launch --------------------------------------------
extern "C" void kernel_launch(void* const* d_in, const int* in_sizes, int n_in,
                              void* d_out, int out_size) {
    const float* vid = (const float*)d_in[0];
    const float* w_theta = (const float*)d_in[1];
    const float* b_theta = (const float*)d_in[2];
    const float* w_phi = (const float*)d_in[3];
    const float* b_phi = (const float*)d_in[4];
    const float* w_g = (const float*)d_in[5];
    const float* b_g = (const float*)d_in[6];
    const float* w_w = (const float*)d_in[7];
    const float* b_w = (const float*)d_in[8];
    const float* w_c33 = (const float*)d_in[9];
    const float* b_c33 = (const float*)d_in[10];
    float* out = (float*)d_out;

    int smem = SMEM_WORDS * 4;
    cudaFuncSetAttribute(attn_kernel, cudaFuncAttributeMaxDynamicSharedMemorySize, smem);

    zero_kernel<<<(Bn * CI * HWn + 255) / 256, 256>>>();
    proj_kernel<<<(Bn * HWn * 3 + 255) / 256, 256>>>(vid, w_theta, b_theta, w_phi, b_phi, w_g, b_g);
    precomp_kernel<<<4, 256>>>(w_w, b_w, w_c33, b_c33);
    attn_kernel<<<Bn * (Qn / 2), 256, smem>>>();
    out_kernel<<<(Bn * HWn * 4 + 255) / 256, 256>>>(vid, w_c33, out);
}